// round 2
// baseline (speedup 1.0000x reference)
#include <cuda_runtime.h>
#include <cuda_bf16.h>
#include <math.h>

#define B_  16
#define N_  1024
#define FIN 128
#define FO  64
#define ALPHA_ 0.2f

// Scratch (device globals: no allocation allowed)
__device__ float g_h[B_ * N_ * FO];           // 4 MB
__device__ float g_s1[B_ * N_], g_p1[B_ * N_], g_q1[B_ * N_];
__device__ float g_s2[B_ * N_], g_p2[B_ * N_], g_q2[B_ * N_];

// ---------------- packed f32x2 helpers (Blackwell FFMA2 path) ----------------
__device__ __forceinline__ unsigned long long pack2(float x, float y) {
    unsigned long long r;
    asm("mov.b64 %0, {%1, %2};" : "=l"(r) : "f"(x), "f"(y));
    return r;
}
__device__ __forceinline__ void unpack2(unsigned long long v, float& x, float& y) {
    asm("mov.b64 {%0, %1}, %2;" : "=f"(x), "=f"(y) : "l"(v));
}
__device__ __forceinline__ unsigned long long fma2(unsigned long long a,
                                                   unsigned long long b,
                                                   unsigned long long c) {
    unsigned long long d;
    asm("fma.rn.f32x2 %0, %1, %2, %3;" : "=l"(d) : "l"(a), "l"(b), "l"(c));
    return d;
}

// ---------------------------------------------------------------------------
// Kernel 1: h = inp @ W.  Block: 64 rows x 64 outputs. Thread: 1 row x 16 out.
// W in smem [k][o]; inp streamed by LDG128 (4 lanes/row share the line).
// ---------------------------------------------------------------------------
__global__ __launch_bounds__(256) void k_h_gemm(const float* __restrict__ inp,
                                                const float* __restrict__ W) {
    __shared__ float sW[FIN * FO];     // 32 KB
    const int b    = blockIdx.y;
    const int row0 = blockIdx.x * 64;
    const int t    = threadIdx.x;

    for (int idx = t; idx < FIN * FO / 4; idx += 256)
        ((float4*)sW)[idx] = ((const float4*)W)[idx];
    __syncthreads();

    const int r  = t >> 2;            // local row 0..63
    const int o0 = (t & 3) << 4;      // output base 0/16/32/48

    const float4* rowp = (const float4*)(inp + ((size_t)b * N_ + row0 + r) * FIN);

    unsigned long long acc2[8];
#pragma unroll
    for (int c = 0; c < 8; c++) acc2[c] = pack2(0.f, 0.f);

    float4 iv4 = rowp[0];
#pragma unroll 8
    for (int kk = 0; kk < FIN; kk += 4) {
        float4 cur = iv4;
        if (kk + 4 < FIN) iv4 = rowp[(kk >> 2) + 1];
        const float ivs[4] = {cur.x, cur.y, cur.z, cur.w};
#pragma unroll
        for (int c = 0; c < 4; c++) {
            const unsigned long long iv2 = pack2(ivs[c], ivs[c]);
            const ulonglong2* w8 = (const ulonglong2*)(sW + (kk + c) * FO + o0);
            ulonglong2 wa = w8[0];
            ulonglong2 wb = w8[1];
            acc2[0] = fma2(iv2, wa.x, acc2[0]);
            acc2[1] = fma2(iv2, wa.y, acc2[1]);
            acc2[2] = fma2(iv2, wb.x, acc2[2]);
            acc2[3] = fma2(iv2, wb.y, acc2[3]);
            w8 = (const ulonglong2*)(sW + (kk + c) * FO + o0 + 8);
            wa = w8[0];
            wb = w8[1];
            acc2[4] = fma2(iv2, wa.x, acc2[4]);
            acc2[5] = fma2(iv2, wa.y, acc2[5]);
            acc2[6] = fma2(iv2, wb.x, acc2[6]);
            acc2[7] = fma2(iv2, wb.y, acc2[7]);
        }
    }

    float* op = g_h + ((size_t)b * N_ + row0 + r) * FO + o0;
#pragma unroll
    for (int c = 0; c < 4; c++) {
        float4 rv;
        unpack2(acc2[2 * c],     rv.x, rv.y);
        unpack2(acc2[2 * c + 1], rv.z, rv.w);
        ((float4*)op)[c] = rv;
    }
}

// ---------------------------------------------------------------------------
// Kernel 2: per-node scores s1 = h@a1, s2 = h@a2, and the 4 exps.
// ---------------------------------------------------------------------------
__global__ __launch_bounds__(256) void k_scores(const float* __restrict__ a) {
    const int warp = (blockIdx.x * 256 + threadIdx.x) >> 5;
    const int lane = threadIdx.x & 31;
    if (warp >= B_ * N_) return;

    const float* hrow = g_h + (size_t)warp * FO;
    const float h0 = hrow[lane];
    const float h1 = hrow[lane + 32];
    float s1 = h0 * a[lane]      + h1 * a[lane + 32];
    float s2 = h0 * a[64 + lane] + h1 * a[96 + lane];
#pragma unroll
    for (int off = 16; off > 0; off >>= 1) {
        s1 += __shfl_xor_sync(0xffffffffu, s1, off);
        s2 += __shfl_xor_sync(0xffffffffu, s2, off);
    }
    if (lane == 0) {
        g_s1[warp] = s1;
        g_p1[warp] = __expf(s1);
        g_q1[warp] = __expf(ALPHA_ * s1);
        g_s2[warp] = s2;
        g_p2[warp] = __expf(s2);
        g_q2[warp] = __expf(ALPHA_ * s2);
    }
}

// ---------------------------------------------------------------------------
// Kernel 3: fused  w_ij = mask * exp(lrelu(s1_i+s2_j)) ;  h' = (w @ h)/Z ; ELU
// TI=64 rows x FO=64 outputs per block, TJ=32 per step.
// Weights stored DUPLICATED as f32x2 {w,w}; z accumulated in w-phase regs.
// ---------------------------------------------------------------------------
__global__ __launch_bounds__(256) void k_attn(const int* __restrict__ adj,
                                              float* __restrict__ out) {
    __shared__ float hs[32 * FO];                       // 8 KB   [j][o]
    __shared__ unsigned long long ws2[64 * 33];         // 16.9KB [i][j] dup'd
    __shared__ float s1s[64], p1s[64], q1s[64], zs[64];
    __shared__ float s2s[N_], p2s[N_], q2s[N_];         // 12 KB

    const int b  = blockIdx.y;
    const int i0 = blockIdx.x * 64;
    const int t  = threadIdx.x;

    if (t < 64) {
        const int gi = b * N_ + i0 + t;
        s1s[t] = g_s1[gi]; p1s[t] = g_p1[gi]; q1s[t] = g_q1[gi];
    }
    for (int idx = t; idx < N_; idx += 256) {
        const int gj = b * N_ + idx;
        s2s[idx] = g_s2[gj]; p2s[idx] = g_p2[gj]; q2s[idx] = g_q2[gj];
    }

    const int ot = t & 15;       // math phase: outputs 4*ot..4*ot+3
    const int it = t >> 4;       // math phase: rows   4*it..4*it+3
    const int jt = t & 31;       // w phase: j column within tile
    const int ib = t >> 5;       // w phase: row group (warp id)

    unsigned long long acc2[4][2];
    float zacc[8];
#pragma unroll
    for (int k = 0; k < 4; k++) {
        acc2[k][0] = pack2(0.f, 0.f);
        acc2[k][1] = pack2(0.f, 0.f);
    }
#pragma unroll
    for (int k = 0; k < 8; k++) zacc[k] = 0.f;

    const int*    adjb = adj + (size_t)b * N_ * N_;
    const float4* hb4  = (const float4*)(g_h + (size_t)b * N_ * FO);

    // prefetch adj tile 0
    int av[8];
#pragma unroll
    for (int k = 0; k < 8; k++)
        av[k] = adjb[(size_t)(i0 + ib * 8 + k) * N_ + jt];

    for (int j0 = 0; j0 < N_; j0 += 32) {
        __syncthreads();   // prev math readers done; also covers s-array preload
        // h tile [32 x 64] = 512 float4
        ((float4*)hs)[t]       = hb4[j0 * 16 + t];
        ((float4*)hs)[t + 256] = hb4[j0 * 16 + t + 256];
        // weights for 64 x 32 tile (duplicated), z partials in regs
        const float s2v = s2s[j0 + jt];
        const float p2v = p2s[j0 + jt];
        const float q2v = q2s[j0 + jt];
#pragma unroll
        for (int k = 0; k < 8; k++) {
            const int il = ib * 8 + k;
            float w = 0.f;
            if (av[k] > 0)
                w = (s1s[il] + s2v > 0.f) ? p1s[il] * p2v : q1s[il] * q2v;
            zacc[k] += w;
            ws2[il * 33 + jt] = pack2(w, w);
        }
        // prefetch next adj tile (lands during math loop)
        if (j0 + 32 < N_) {
#pragma unroll
            for (int k = 0; k < 8; k++)
                av[k] = adjb[(size_t)(i0 + ib * 8 + k) * N_ + j0 + 32 + jt];
        }
        __syncthreads();
        // accumulate: 4i x 4o tile, packed f32x2
        const ulonglong2* hs8 = (const ulonglong2*)hs;
#pragma unroll 8
        for (int jj = 0; jj < 32; jj++) {
            const ulonglong2 hv = hs8[jj * 16 + ot];
#pragma unroll
            for (int k = 0; k < 4; k++) {
                const unsigned long long ww = ws2[(it * 4 + k) * 33 + jj];
                acc2[k][0] = fma2(ww, hv.x, acc2[k][0]);
                acc2[k][1] = fma2(ww, hv.y, acc2[k][1]);
            }
        }
    }

    // reduce z partials: warp ib owns rows ib*8..ib*8+7, lanes = j columns
#pragma unroll
    for (int k = 0; k < 8; k++) {
        float v = zacc[k];
#pragma unroll
        for (int off = 16; off > 0; off >>= 1)
            v += __shfl_xor_sync(0xffffffffu, v, off);
        if (jt == 0) zs[ib * 8 + k] = v;
    }
    __syncthreads();

    // normalize + ELU + store
#pragma unroll
    for (int k = 0; k < 4; k++) {
        const int i   = i0 + it * 4 + k;
        const float inv = 1.f / zs[it * 4 + k];
        float x0, x1, x2, x3;
        unpack2(acc2[k][0], x0, x1);
        unpack2(acc2[k][1], x2, x3);
        float4 r;
        float v;
        v = x0 * inv; r.x = (v > 0.f) ? v : expm1f(v);
        v = x1 * inv; r.y = (v > 0.f) ? v : expm1f(v);
        v = x2 * inv; r.z = (v > 0.f) ? v : expm1f(v);
        v = x3 * inv; r.w = (v > 0.f) ? v : expm1f(v);
        ((float4*)out)[((size_t)b * N_ + i) * 16 + ot] = r;
    }
}

// ---------------------------------------------------------------------------
extern "C" void kernel_launch(void* const* d_in, const int* in_sizes, int n_in,
                              void* d_out, int out_size) {
    const float* inp = (const float*)d_in[0];   // (16,1024,128) f32
    const int*   adj = (const int*)d_in[1];     // (16,1024,1024) i32
    const float* W   = (const float*)d_in[2];   // (128,64) f32
    const float* a   = (const float*)d_in[3];   // (128,1) f32
    float* out = (float*)d_out;                 // (16,1024,64) f32

    k_h_gemm<<<dim3(N_ / 64, B_), 256>>>(inp, W);
    k_scores<<<(B_ * N_ * 32 + 255) / 256, 256>>>(a);
    k_attn<<<dim3(N_ / 64, B_), 256>>>(adj, out);
}

// round 4
// speedup vs baseline: 1.8328x; 1.8328x over previous
#include <cuda_runtime.h>
#include <cuda_bf16.h>
#include <math.h>
#include <stdint.h>

#define B_  16
#define N_  1024
#define FIN 128
#define FO  64
#define ALPHA_ 0.2f

// Scratch (device globals: no allocation allowed)
__device__ float g_h[B_ * N_ * FO];           // 4 MB  [b][j][o]
__device__ float g_s1[B_ * N_], g_p1[B_ * N_], g_q1[B_ * N_];
__device__ float g_s2[B_ * N_], g_p2[B_ * N_], g_q2[B_ * N_];

__device__ __forceinline__ float to_tf32(float x) {
    float r;
    asm("cvt.rna.tf32.f32 %0, %1;" : "=f"(r) : "f"(x));
    return r;
}
__device__ __forceinline__ void mma_tf32(float* d, const uint32_t* a,
                                         uint32_t b0, uint32_t b1) {
    asm volatile(
        "mma.sync.aligned.m16n8k8.row.col.f32.tf32.tf32.f32 "
        "{%0,%1,%2,%3}, {%4,%5,%6,%7}, {%8,%9}, {%0,%1,%2,%3};"
        : "+f"(d[0]), "+f"(d[1]), "+f"(d[2]), "+f"(d[3])
        : "r"(a[0]), "r"(a[1]), "r"(a[2]), "r"(a[3]), "r"(b0), "r"(b1));
}

// smem byte offsets for k_attn (dynamic smem)
#define WS_OFF   0          // float ws[128][68]  = 34816 B
#define HS_OFF   34816      // float hs[64][72]   = 18432 B
#define S2_OFF   53248      // float s2s[1024]
#define P2_OFF   57344
#define Q2_OFF   61440
#define ZP_OFF   65536      // float zpart[256]
#define ZS_OFF   66560      // float zs[128]
#define SMEM_ATTN 67584

// ---------------------------------------------------------------------------
// Kernel 1: h = inp @ W (round-0 proven version)
// ---------------------------------------------------------------------------
__global__ __launch_bounds__(256) void k_h_gemm(const float* __restrict__ inp,
                                                const float* __restrict__ W) {
    __shared__ float sW[FIN * FO];     // 32 KB
    __shared__ float sI[32 * FIN];     // 16 KB
    const int b = blockIdx.y;
    const int row0 = blockIdx.x * 32;
    const int t = threadIdx.x;

    for (int idx = t; idx < FIN * FO; idx += 256) sW[idx] = W[idx];
    const float4* ip = (const float4*)(inp + ((size_t)b * N_ + row0) * FIN);
    for (int idx = t; idx < 32 * FIN / 4; idx += 256) ((float4*)sI)[idx] = ip[idx];
    __syncthreads();

    const int o = t & 63;
    const int rg = t >> 6;
    float acc[8];
#pragma unroll
    for (int r = 0; r < 8; r++) acc[r] = 0.f;

#pragma unroll 4
    for (int k = 0; k < FIN; k++) {
        const float wv = sW[k * FO + o];
#pragma unroll
        for (int r = 0; r < 8; r++)
            acc[r] += sI[(rg * 8 + r) * FIN + k] * wv;
    }
#pragma unroll
    for (int r = 0; r < 8; r++) {
        const int row = row0 + rg * 8 + r;
        g_h[((size_t)b * N_ + row) * FO + o] = acc[r];
    }
}

// ---------------------------------------------------------------------------
// Kernel 2: per-node scores + 4 exps
// ---------------------------------------------------------------------------
__global__ __launch_bounds__(256) void k_scores(const float* __restrict__ a) {
    const int warp = (blockIdx.x * 256 + threadIdx.x) >> 5;
    const int lane = threadIdx.x & 31;
    if (warp >= B_ * N_) return;

    const float* hrow = g_h + (size_t)warp * FO;
    const float h0 = hrow[lane];
    const float h1 = hrow[lane + 32];
    float s1 = h0 * a[lane]      + h1 * a[lane + 32];
    float s2 = h0 * a[64 + lane] + h1 * a[96 + lane];
#pragma unroll
    for (int off = 16; off > 0; off >>= 1) {
        s1 += __shfl_xor_sync(0xffffffffu, s1, off);
        s2 += __shfl_xor_sync(0xffffffffu, s2, off);
    }
    if (lane == 0) {
        g_s1[warp] = s1;
        g_p1[warp] = __expf(s1);
        g_q1[warp] = __expf(ALPHA_ * s1);
        g_s2[warp] = s2;
        g_p2[warp] = __expf(s2);
        g_q2[warp] = __expf(ALPHA_ * s2);
    }
}

// ---------------------------------------------------------------------------
// Kernel 3: attention via mma.sync tf32. CTA: 128 i-rows x 64 outputs.
// Per 64-j tile: gen w (tf32) -> ws, stage h (tf32) -> hs, 8 warps MMA.
// z accumulated exactly in fp32; only numerator goes through tf32.
// ---------------------------------------------------------------------------
__global__ __launch_bounds__(256) void k_attn(const int* __restrict__ adj,
                                              float* __restrict__ out) {
    extern __shared__ char sm[];
    float* ws  = (float*)(sm + WS_OFF);    // [128][68]
    float* hs  = (float*)(sm + HS_OFF);    // [64][72]
    float* s2s = (float*)(sm + S2_OFF);
    float* p2s = (float*)(sm + P2_OFF);
    float* q2s = (float*)(sm + Q2_OFF);
    float* zp  = (float*)(sm + ZP_OFF);
    float* zs  = (float*)(sm + ZS_OFF);

    const int b  = blockIdx.y;
    const int i0 = blockIdx.x * 128;
    const int t  = threadIdx.x;

    // preload per-j score tables for this batch
    for (int idx = t; idx < N_; idx += 256) {
        const int gj = b * N_ + idx;
        s2s[idx] = g_s2[gj]; p2s[idx] = g_p2[gj]; q2s[idx] = g_q2[gj];
    }

    // gen-phase mapping: row i = t&127, j-half = (t>>7)*32
    const int ir = t & 127;
    const int jh = (t >> 7) * 32;
    const int gi = b * N_ + i0 + ir;
    const float s1r = g_s1[gi], p1r = g_p1[gi], q1r = g_q1[gi];
    const int* adjrow = adj + (size_t)b * N_ * N_ + (size_t)(i0 + ir) * N_ + jh;

    // mma-phase mapping: warp tile 32i x 32o
    const int wid  = t >> 5;
    const int lane = t & 31;
    const int g    = lane >> 2;
    const int tid4 = lane & 3;
    const int m0   = (wid & 3) * 32;
    const int n0   = (wid >> 2) * 32;

    float acc[2][4][4];
#pragma unroll
    for (int mt = 0; mt < 2; mt++)
#pragma unroll
        for (int nf = 0; nf < 4; nf++)
#pragma unroll
            for (int c = 0; c < 4; c++) acc[mt][nf][c] = 0.f;

    const float4* hb4 = (const float4*)(g_h + (size_t)b * N_ * FO);

    int4 av[8];
#pragma unroll
    for (int k = 0; k < 8; k++) av[k] = ((const int4*)adjrow)[k];

    float zacc = 0.f;

    for (int tile = 0; tile < 16; tile++) {
        __syncthreads();   // prev mma done reading ws/hs (tile0: tables ready)

        // ---- generate w: rows 0..127, this thread's 32 j's ----
        const int sbase = tile * 64 + jh;
        float* wrow = ws + ir * 68 + jh;
#pragma unroll
        for (int k = 0; k < 8; k++) {
            const float4 s2v = *(const float4*)(s2s + sbase + k * 4);
            const float4 p2v = *(const float4*)(p2s + sbase + k * 4);
            const float4 q2v = *(const float4*)(q2s + sbase + k * 4);
            const int4 a = av[k];
            float4 wq;
            float w;
            w = 0.f; if (a.x > 0) w = (s1r + s2v.x > 0.f) ? p1r * p2v.x : q1r * q2v.x;
            zacc += w; wq.x = to_tf32(w);
            w = 0.f; if (a.y > 0) w = (s1r + s2v.y > 0.f) ? p1r * p2v.y : q1r * q2v.y;
            zacc += w; wq.y = to_tf32(w);
            w = 0.f; if (a.z > 0) w = (s1r + s2v.z > 0.f) ? p1r * p2v.z : q1r * q2v.z;
            zacc += w; wq.z = to_tf32(w);
            w = 0.f; if (a.w > 0) w = (s1r + s2v.w > 0.f) ? p1r * p2v.w : q1r * q2v.w;
            zacc += w; wq.w = to_tf32(w);
            *(float4*)(wrow + k * 4) = wq;
        }

        // ---- stage h tile [64 j][64 o] -> hs (tf32), stride 72 ----
#pragma unroll
        for (int k = 0; k < 4; k++) {
            const int l = t + k * 256;          // 0..1023 float4 units
            const int j = l >> 4, o4 = l & 15;
            float4 hv = hb4[tile * 1024 + l];
            hv.x = to_tf32(hv.x); hv.y = to_tf32(hv.y);
            hv.z = to_tf32(hv.z); hv.w = to_tf32(hv.w);
            ((float4*)hs)[j * 18 + o4] = hv;
        }

        // ---- prefetch next adj tile ----
        if (tile < 15) {
            const int* nx = adjrow + (tile + 1) * 64;
#pragma unroll
            for (int k = 0; k < 8; k++) av[k] = ((const int4*)nx)[k];
        }

        __syncthreads();

        // ---- MMA: 8 k-steps over this 64-j tile ----
#pragma unroll
        for (int ks = 0; ks < 8; ks++) {
            const int k0 = ks * 8;
            uint32_t A[2][4];
#pragma unroll
            for (int mt = 0; mt < 2; mt++) {
                const int r0 = m0 + mt * 16 + g;
                A[mt][0] = __float_as_uint(ws[r0 * 68 + k0 + tid4]);
                A[mt][1] = __float_as_uint(ws[(r0 + 8) * 68 + k0 + tid4]);
                A[mt][2] = __float_as_uint(ws[r0 * 68 + k0 + tid4 + 4]);
                A[mt][3] = __float_as_uint(ws[(r0 + 8) * 68 + k0 + tid4 + 4]);
            }
#pragma unroll
            for (int nf = 0; nf < 4; nf++) {
                const int c0 = n0 + nf * 8 + g;
                const uint32_t b0 = __float_as_uint(hs[(k0 + tid4) * 72 + c0]);
                const uint32_t b1 = __float_as_uint(hs[(k0 + tid4 + 4) * 72 + c0]);
                mma_tf32(acc[0][nf], A[0], b0, b1);
                mma_tf32(acc[1][nf], A[1], b0, b1);
            }
        }
    }

    // ---- z: combine the two half-partials per row ----
    zp[t] = zacc;
    __syncthreads();
    if (t < 128) zs[t] = zp[t] + zp[t + 128];
    __syncthreads();

    // ---- epilogue: normalize + ELU + store ----
#pragma unroll
    for (int mt = 0; mt < 2; mt++) {
        const int rA = m0 + mt * 16 + g;
        const int rB = rA + 8;
        const float invA = 1.f / zs[rA];
        const float invB = 1.f / zs[rB];
        float* outA = out + ((size_t)(b * N_ + i0 + rA)) * FO;
        float* outB = out + ((size_t)(b * N_ + i0 + rB)) * FO;
#pragma unroll
        for (int nf = 0; nf < 4; nf++) {
            const int col = n0 + nf * 8 + 2 * tid4;
            float v;
            float2 r;
            v = acc[mt][nf][0] * invA; r.x = (v > 0.f) ? v : expm1f(v);
            v = acc[mt][nf][1] * invA; r.y = (v > 0.f) ? v : expm1f(v);
            *(float2*)(outA + col) = r;
            v = acc[mt][nf][2] * invB; r.x = (v > 0.f) ? v : expm1f(v);
            v = acc[mt][nf][3] * invB; r.y = (v > 0.f) ? v : expm1f(v);
            *(float2*)(outB + col) = r;
        }
    }
}

// ---------------------------------------------------------------------------
extern "C" void kernel_launch(void* const* d_in, const int* in_sizes, int n_in,
                              void* d_out, int out_size) {
    const float* inp = (const float*)d_in[0];   // (16,1024,128) f32
    const int*   adj = (const int*)d_in[1];     // (16,1024,1024) i32
    const float* W   = (const float*)d_in[2];   // (128,64) f32
    const float* a   = (const float*)d_in[3];   // (128,1) f32
    float* out = (float*)d_out;                 // (16,1024,64) f32

    static int init = 0;
    if (!init) {
        cudaFuncSetAttribute(k_attn, cudaFuncAttributeMaxDynamicSharedMemorySize,
                             SMEM_ATTN);
        init = 1;
    }

    k_h_gemm<<<dim3(N_ / 32, B_), 256>>>(inp, W);
    k_scores<<<(B_ * N_ * 32 + 255) / 256, 256>>>(a);
    k_attn<<<dim3(N_ / 128, B_), 256, SMEM_ATTN>>>(adj, out);
}

// round 5
// speedup vs baseline: 2.2619x; 1.2341x over previous
#include <cuda_runtime.h>
#include <cuda_bf16.h>
#include <math.h>
#include <stdint.h>

#define B_  16
#define N_  1024
#define FIN 128
#define FO  64
#define ALPHA_ 0.2f

// Scratch (device globals: no allocation allowed)
__device__ float g_h[B_ * N_ * FO];           // 4 MB  [b][j][o]
__device__ float g_s1[B_ * N_], g_p1[B_ * N_], g_q1[B_ * N_];
__device__ float g_s2[B_ * N_], g_p2[B_ * N_], g_q2[B_ * N_];

__device__ __forceinline__ float to_tf32(float x) {
    float r;
    asm("cvt.rna.tf32.f32 %0, %1;" : "=f"(r) : "f"(x));
    return r;
}
__device__ __forceinline__ void mma_tf32(float* d, const uint32_t* a,
                                         uint32_t b0, uint32_t b1) {
    asm volatile(
        "mma.sync.aligned.m16n8k8.row.col.f32.tf32.tf32.f32 "
        "{%0,%1,%2,%3}, {%4,%5,%6,%7}, {%8,%9}, {%0,%1,%2,%3};"
        : "+f"(d[0]), "+f"(d[1]), "+f"(d[2]), "+f"(d[3])
        : "r"(a[0]), "r"(a[1]), "r"(a[2]), "r"(a[3]), "r"(b0), "r"(b1));
}

// smem byte offsets for k_attn
#define WS_OFF   0          // float ws[128][68]  = 34816 B
#define HS_OFF   34816      // float hs[64][72]   = 18432 B
#define S2_OFF   53248
#define P2_OFF   57344
#define Q2_OFF   61440
#define ZP_OFF   65536      // float zp[512]
#define ZS_OFF   67584      // float zs[128]
#define SMEM_ATTN 68096

#define SMEM_HG  66048      // sI 32K + sW 32K + sA 512

// ---------------------------------------------------------------------------
// Kernel 1: h = inp @ W, fused with per-node score computation (s1,s2 + exps).
// CTA: 64 rows x 64 outs, 256 threads; thread = 4 rows x 4 outs.
// ---------------------------------------------------------------------------
__global__ __launch_bounds__(256) void k_h_gemm(const float* __restrict__ inp,
                                                const float* __restrict__ W,
                                                const float* __restrict__ a) {
    extern __shared__ char sm1[];
    float* sI = (float*)sm1;             // [64][128] 32 KB
    float* sW = (float*)(sm1 + 32768);   // [128][64] 32 KB
    float* sA = (float*)(sm1 + 65536);   // [128]

    const int b    = blockIdx.y;
    const int row0 = blockIdx.x * 64;
    const int t    = threadIdx.x;

#pragma unroll
    for (int k = 0; k < 8; k++)
        ((float4*)sW)[t + k * 256] = ((const float4*)W)[t + k * 256];
    const float4* ip = (const float4*)(inp + ((size_t)b * N_ + row0) * FIN);
#pragma unroll
    for (int k = 0; k < 8; k++)
        ((float4*)sI)[t + k * 256] = ip[t + k * 256];
    if (t < 128) sA[t] = a[t];
    __syncthreads();

    const int ot = t & 15;       // outs 4*ot..4*ot+3
    const int rt = t >> 4;       // rows 4*rt..4*rt+3
    const int lane = t & 31;

    float acc[4][4];
#pragma unroll
    for (int r = 0; r < 4; r++)
#pragma unroll
        for (int c = 0; c < 4; c++) acc[r][c] = 0.f;

#pragma unroll 4
    for (int k = 0; k < FIN; k++) {
        const float4 w4 = *(const float4*)(sW + k * FO + ot * 4);
#pragma unroll
        for (int r = 0; r < 4; r++) {
            const float iv = sI[(rt * 4 + r) * FIN + k];
            acc[r][0] += iv * w4.x;
            acc[r][1] += iv * w4.y;
            acc[r][2] += iv * w4.z;
            acc[r][3] += iv * w4.w;
        }
    }

    // store h
#pragma unroll
    for (int r = 0; r < 4; r++) {
        float* op = g_h + ((size_t)b * N_ + row0 + rt * 4 + r) * FO + ot * 4;
        *(float4*)op = make_float4(acc[r][0], acc[r][1], acc[r][2], acc[r][3]);
    }

    // fused scores: s1 = h.a1, s2 = h.a2 (reduce over the 16 o-threads)
    float s1p[4], s2p[4];
#pragma unroll
    for (int r = 0; r < 4; r++) {
        float v1 = 0.f, v2 = 0.f;
#pragma unroll
        for (int c = 0; c < 4; c++) {
            v1 += acc[r][c] * sA[ot * 4 + c];
            v2 += acc[r][c] * sA[64 + ot * 4 + c];
        }
        s1p[r] = v1; s2p[r] = v2;
    }
#pragma unroll
    for (int off = 8; off > 0; off >>= 1) {
#pragma unroll
        for (int r = 0; r < 4; r++) {
            s1p[r] += __shfl_xor_sync(0xffffffffu, s1p[r], off);
            s2p[r] += __shfl_xor_sync(0xffffffffu, s2p[r], off);
        }
    }
    if ((lane & 15) == 0) {
#pragma unroll
        for (int r = 0; r < 4; r++) {
            const int gi = b * N_ + row0 + rt * 4 + r;
            const float s1 = s1p[r], s2 = s2p[r];
            g_s1[gi] = s1;
            g_p1[gi] = __expf(s1);
            g_q1[gi] = __expf(ALPHA_ * s1);
            g_s2[gi] = s2;
            g_p2[gi] = __expf(s2);
            g_q2[gi] = __expf(ALPHA_ * s2);
        }
    }
}

// ---------------------------------------------------------------------------
// Kernel 2: attention via mma.sync tf32. CTA: 128 i-rows x 64 outs, 512 thr.
// z accumulated exactly in fp32; only the numerator goes through tf32.
// ---------------------------------------------------------------------------
__global__ __launch_bounds__(512) void k_attn(const int* __restrict__ adj,
                                              float* __restrict__ out) {
    extern __shared__ char sm[];
    float* ws  = (float*)(sm + WS_OFF);    // [128][68]
    float* hs  = (float*)(sm + HS_OFF);    // [64][72]
    float* s2s = (float*)(sm + S2_OFF);
    float* p2s = (float*)(sm + P2_OFF);
    float* q2s = (float*)(sm + Q2_OFF);
    float* zp  = (float*)(sm + ZP_OFF);
    float* zs  = (float*)(sm + ZS_OFF);

    const int b  = blockIdx.y;
    const int i0 = blockIdx.x * 128;
    const int t  = threadIdx.x;

    for (int idx = t; idx < N_; idx += 512) {
        const int gj = b * N_ + idx;
        s2s[idx] = g_s2[gj]; p2s[idx] = g_p2[gj]; q2s[idx] = g_q2[gj];
    }

    // gen mapping: row ir = t&127, j-chunk jh = (t>>7)*16 (16 j's per thread)
    const int ir = t & 127;
    const int jh = (t >> 7) * 16;
    const int gi = b * N_ + i0 + ir;
    const float s1r = g_s1[gi], p1r = g_p1[gi], q1r = g_q1[gi];
    const int* adjrow = adj + (size_t)b * N_ * N_ + (size_t)(i0 + ir) * N_ + jh;

    // mma mapping: 16 warps, warp tile 32i x 16o
    const int wid  = t >> 5;
    const int lane = t & 31;
    const int g    = lane >> 2;
    const int tid4 = lane & 3;
    const int m0   = (wid & 3) * 32;
    const int n0   = (wid >> 2) * 16;

    float acc[2][2][4];
#pragma unroll
    for (int mt = 0; mt < 2; mt++)
#pragma unroll
        for (int nf = 0; nf < 2; nf++)
#pragma unroll
            for (int c = 0; c < 4; c++) acc[mt][nf][c] = 0.f;

    const float4* hb4 = (const float4*)(g_h + (size_t)b * N_ * FO);

    int4 av[4], avn[4];
#pragma unroll
    for (int k = 0; k < 4; k++) av[k] = ((const int4*)adjrow)[k];

    float zacc = 0.f;

    for (int tile = 0; tile < 16; tile++) {
        __syncthreads();   // prev MMA done reading ws/hs (tile0: tables ready)

        // issue h-tile loads early (L2-resident after first i-tile)
        float4 hv0 = hb4[tile * 1024 + t];
        float4 hv1 = hb4[tile * 1024 + t + 512];
        // issue next adj tile loads early
        if (tile < 15) {
            const int* nx = adjrow + (tile + 1) * 64;
#pragma unroll
            for (int k = 0; k < 4; k++) avn[k] = ((const int4*)nx)[k];
        }

        // ---- generate w: this thread's row, 16 j's ----
        const int sbase = tile * 64 + jh;
        float* wrow = ws + ir * 68 + jh;
#pragma unroll
        for (int k = 0; k < 4; k++) {
            const float4 s2v = *(const float4*)(s2s + sbase + k * 4);
            const float4 p2v = *(const float4*)(p2s + sbase + k * 4);
            const float4 q2v = *(const float4*)(q2s + sbase + k * 4);
            const int4 a = av[k];
            float4 wq;
            float w;
            w = 0.f; if (a.x > 0) w = (s1r + s2v.x > 0.f) ? p1r * p2v.x : q1r * q2v.x;
            zacc += w; wq.x = to_tf32(w);
            w = 0.f; if (a.y > 0) w = (s1r + s2v.y > 0.f) ? p1r * p2v.y : q1r * q2v.y;
            zacc += w; wq.y = to_tf32(w);
            w = 0.f; if (a.z > 0) w = (s1r + s2v.z > 0.f) ? p1r * p2v.z : q1r * q2v.z;
            zacc += w; wq.z = to_tf32(w);
            w = 0.f; if (a.w > 0) w = (s1r + s2v.w > 0.f) ? p1r * p2v.w : q1r * q2v.w;
            zacc += w; wq.w = to_tf32(w);
            *(float4*)(wrow + k * 4) = wq;
        }

        // ---- stage h tile [64 j][64 o] (tf32), stride 72 floats ----
        {
            int l = t;
            hv0.x = to_tf32(hv0.x); hv0.y = to_tf32(hv0.y);
            hv0.z = to_tf32(hv0.z); hv0.w = to_tf32(hv0.w);
            ((float4*)hs)[(l >> 4) * 18 + (l & 15)] = hv0;
            l = t + 512;
            hv1.x = to_tf32(hv1.x); hv1.y = to_tf32(hv1.y);
            hv1.z = to_tf32(hv1.z); hv1.w = to_tf32(hv1.w);
            ((float4*)hs)[(l >> 4) * 18 + (l & 15)] = hv1;
        }

#pragma unroll
        for (int k = 0; k < 4; k++) av[k] = avn[k];

        __syncthreads();

        // ---- MMA: 8 k-steps over this 64-j tile ----
#pragma unroll
        for (int ks = 0; ks < 8; ks++) {
            const int k0 = ks * 8;
            uint32_t A[2][4];
#pragma unroll
            for (int mt = 0; mt < 2; mt++) {
                const int r0 = m0 + mt * 16 + g;
                A[mt][0] = __float_as_uint(ws[r0 * 68 + k0 + tid4]);
                A[mt][1] = __float_as_uint(ws[(r0 + 8) * 68 + k0 + tid4]);
                A[mt][2] = __float_as_uint(ws[r0 * 68 + k0 + tid4 + 4]);
                A[mt][3] = __float_as_uint(ws[(r0 + 8) * 68 + k0 + tid4 + 4]);
            }
#pragma unroll
            for (int nf = 0; nf < 2; nf++) {
                const int c0 = n0 + nf * 8 + g;
                const uint32_t b0 = __float_as_uint(hs[(k0 + tid4) * 72 + c0]);
                const uint32_t b1 = __float_as_uint(hs[(k0 + tid4 + 4) * 72 + c0]);
                mma_tf32(acc[0][nf], A[0], b0, b1);
                mma_tf32(acc[1][nf], A[1], b0, b1);
            }
        }
    }

    // ---- z: combine the four quarter-partials per row ----
    zp[t] = zacc;
    __syncthreads();
    if (t < 128) zs[t] = (zp[t] + zp[t + 128]) + (zp[t + 256] + zp[t + 384]);
    __syncthreads();

    // ---- epilogue: normalize + ELU + store ----
#pragma unroll
    for (int mt = 0; mt < 2; mt++) {
        const int rA = m0 + mt * 16 + g;
        const int rB = rA + 8;
        const float invA = 1.f / zs[rA];
        const float invB = 1.f / zs[rB];
        float* outA = out + ((size_t)(b * N_ + i0 + rA)) * FO;
        float* outB = out + ((size_t)(b * N_ + i0 + rB)) * FO;
#pragma unroll
        for (int nf = 0; nf < 2; nf++) {
            const int col = n0 + nf * 8 + 2 * tid4;
            float v;
            float2 r;
            v = acc[mt][nf][0] * invA; r.x = (v > 0.f) ? v : expm1f(v);
            v = acc[mt][nf][1] * invA; r.y = (v > 0.f) ? v : expm1f(v);
            *(float2*)(outA + col) = r;
            v = acc[mt][nf][2] * invB; r.x = (v > 0.f) ? v : expm1f(v);
            v = acc[mt][nf][3] * invB; r.y = (v > 0.f) ? v : expm1f(v);
            *(float2*)(outB + col) = r;
        }
    }
}

// ---------------------------------------------------------------------------
extern "C" void kernel_launch(void* const* d_in, const int* in_sizes, int n_in,
                              void* d_out, int out_size) {
    const float* inp = (const float*)d_in[0];   // (16,1024,128) f32
    const int*   adj = (const int*)d_in[1];     // (16,1024,1024) i32
    const float* W   = (const float*)d_in[2];   // (128,64) f32
    const float* a   = (const float*)d_in[3];   // (128,1) f32
    float* out = (float*)d_out;                 // (16,1024,64) f32

    static int init = 0;
    if (!init) {
        cudaFuncSetAttribute(k_h_gemm, cudaFuncAttributeMaxDynamicSharedMemorySize,
                             SMEM_HG);
        cudaFuncSetAttribute(k_attn, cudaFuncAttributeMaxDynamicSharedMemorySize,
                             SMEM_ATTN);
        init = 1;
    }

    k_h_gemm<<<dim3(N_ / 64, B_), 256, SMEM_HG>>>(inp, W, a);
    k_attn<<<dim3(N_ / 128, B_), 512, SMEM_ATTN>>>(adj, out);
}

// round 6
// speedup vs baseline: 2.2758x; 1.0061x over previous
#include <cuda_runtime.h>
#include <cuda_bf16.h>
#include <math.h>
#include <stdint.h>

#define B_  16
#define N_  1024
#define FIN 128
#define FO  64
#define ALPHA_ 0.2f

// Scratch (device globals: no allocation allowed)
__device__ float g_h[B_ * N_ * FO];           // 4 MB  [b][j][o]
__device__ float g_s1[B_ * N_], g_p1[B_ * N_], g_q1[B_ * N_];
__device__ float g_s2[B_ * N_], g_p2[B_ * N_], g_q2[B_ * N_];

__device__ __forceinline__ float to_tf32(float x) {
    float r;
    asm("cvt.rna.tf32.f32 %0, %1;" : "=f"(r) : "f"(x));
    return r;
}
__device__ __forceinline__ void mma_tf32(float* d, const uint32_t* a,
                                         uint32_t b0, uint32_t b1) {
    asm volatile(
        "mma.sync.aligned.m16n8k8.row.col.f32.tf32.tf32.f32 "
        "{%0,%1,%2,%3}, {%4,%5,%6,%7}, {%8,%9}, {%0,%1,%2,%3};"
        : "+f"(d[0]), "+f"(d[1]), "+f"(d[2]), "+f"(d[3])
        : "r"(a[0]), "r"(a[1]), "r"(a[2]), "r"(a[3]), "r"(b0), "r"(b1));
}

// smem byte offsets for k_attn (double-buffered ws/hs)
#define WS0_OFF  0          // float ws[128][68] = 34816 B
#define WS1_OFF  34816
#define HS0_OFF  69632      // float hs[64][72]  = 18432 B
#define HS1_OFF  88064
#define S2_OFF   106496
#define P2_OFF   110592
#define Q2_OFF   114688
#define ZP_OFF   118784     // float zp[512]
#define ZS_OFF   120832     // float zs[128]
#define SMEM_ATTN 121344

#define SMEM_HG  66048      // sI 32K + sW 32K + sA 512

// ---------------------------------------------------------------------------
// Kernel 1: h = inp @ W, fused with per-node scores (s1,s2 + exps).
// ---------------------------------------------------------------------------
__global__ __launch_bounds__(256) void k_h_gemm(const float* __restrict__ inp,
                                                const float* __restrict__ W,
                                                const float* __restrict__ a) {
    extern __shared__ char sm1[];
    float* sI = (float*)sm1;             // [64][128]
    float* sW = (float*)(sm1 + 32768);   // [128][64]
    float* sA = (float*)(sm1 + 65536);   // [128]

    const int b    = blockIdx.y;
    const int row0 = blockIdx.x * 64;
    const int t    = threadIdx.x;

#pragma unroll
    for (int k = 0; k < 8; k++)
        ((float4*)sW)[t + k * 256] = ((const float4*)W)[t + k * 256];
    const float4* ip = (const float4*)(inp + ((size_t)b * N_ + row0) * FIN);
#pragma unroll
    for (int k = 0; k < 8; k++)
        ((float4*)sI)[t + k * 256] = ip[t + k * 256];
    if (t < 128) sA[t] = a[t];
    __syncthreads();

    const int ot = t & 15;
    const int rt = t >> 4;
    const int lane = t & 31;

    float acc[4][4];
#pragma unroll
    for (int r = 0; r < 4; r++)
#pragma unroll
        for (int c = 0; c < 4; c++) acc[r][c] = 0.f;

#pragma unroll 4
    for (int k = 0; k < FIN; k++) {
        const float4 w4 = *(const float4*)(sW + k * FO + ot * 4);
#pragma unroll
        for (int r = 0; r < 4; r++) {
            const float iv = sI[(rt * 4 + r) * FIN + k];
            acc[r][0] += iv * w4.x;
            acc[r][1] += iv * w4.y;
            acc[r][2] += iv * w4.z;
            acc[r][3] += iv * w4.w;
        }
    }

#pragma unroll
    for (int r = 0; r < 4; r++) {
        float* op = g_h + ((size_t)b * N_ + row0 + rt * 4 + r) * FO + ot * 4;
        *(float4*)op = make_float4(acc[r][0], acc[r][1], acc[r][2], acc[r][3]);
    }

    float s1p[4], s2p[4];
#pragma unroll
    for (int r = 0; r < 4; r++) {
        float v1 = 0.f, v2 = 0.f;
#pragma unroll
        for (int c = 0; c < 4; c++) {
            v1 += acc[r][c] * sA[ot * 4 + c];
            v2 += acc[r][c] * sA[64 + ot * 4 + c];
        }
        s1p[r] = v1; s2p[r] = v2;
    }
#pragma unroll
    for (int off = 8; off > 0; off >>= 1) {
#pragma unroll
        for (int r = 0; r < 4; r++) {
            s1p[r] += __shfl_xor_sync(0xffffffffu, s1p[r], off);
            s2p[r] += __shfl_xor_sync(0xffffffffu, s2p[r], off);
        }
    }
    if ((lane & 15) == 0) {
#pragma unroll
        for (int r = 0; r < 4; r++) {
            const int gi = b * N_ + row0 + rt * 4 + r;
            const float s1 = s1p[r], s2 = s2p[r];
            g_s1[gi] = s1;
            g_p1[gi] = __expf(s1);
            g_q1[gi] = __expf(ALPHA_ * s1);
            g_s2[gi] = s2;
            g_p2[gi] = __expf(s2);
            g_q2[gi] = __expf(ALPHA_ * s2);
        }
    }
}

// ---------------------------------------------------------------------------
// Kernel 2: attention via mma.sync tf32, software-pipelined.
// CTA: 128 i x 64 o, 512 thr. Per iter: gen(tile+1) + MMA(tile), ONE barrier.
// ---------------------------------------------------------------------------
__global__ __launch_bounds__(512) void k_attn(const int* __restrict__ adj,
                                              float* __restrict__ out) {
    extern __shared__ char sm[];
    float* s2s = (float*)(sm + S2_OFF);
    float* p2s = (float*)(sm + P2_OFF);
    float* q2s = (float*)(sm + Q2_OFF);
    float* zp  = (float*)(sm + ZP_OFF);
    float* zs  = (float*)(sm + ZS_OFF);

    const int b  = blockIdx.y;
    const int i0 = blockIdx.x * 128;
    const int t  = threadIdx.x;

    for (int idx = t; idx < N_; idx += 512) {
        const int gj = b * N_ + idx;
        s2s[idx] = g_s2[gj]; p2s[idx] = g_p2[gj]; q2s[idx] = g_q2[gj];
    }

    // gen mapping: row ir, 16 j's at jh
    const int ir = t & 127;
    const int jh = (t >> 7) * 16;
    const int gi = b * N_ + i0 + ir;
    const float s1r = g_s1[gi], p1r = g_p1[gi], q1r = g_q1[gi];
    const int* adjrow = adj + (size_t)b * N_ * N_ + (size_t)(i0 + ir) * N_ + jh;

    // mma mapping: 16 warps, warp tile 32i x 16o
    const int wid  = t >> 5;
    const int lane = t & 31;
    const int g    = lane >> 2;
    const int tid4 = lane & 3;
    const int m0   = (wid & 3) * 32;
    const int n0   = (wid >> 2) * 16;

    float acc[2][2][4];
#pragma unroll
    for (int mt = 0; mt < 2; mt++)
#pragma unroll
        for (int nf = 0; nf < 2; nf++)
#pragma unroll
            for (int c = 0; c < 4; c++) acc[mt][nf][c] = 0.f;

    const float4* hb4 = (const float4*)(g_h + (size_t)b * N_ * FO);

    int4 av[4], avn[4];
#pragma unroll
    for (int k = 0; k < 4; k++) av[k] = ((const int4*)adjrow)[k];        // adj(0)

    float zacc = 0.f;
    __syncthreads();   // tables ready

    // ---- gen(tile tt) into buffer bs ----
#define GEN_TILE(tt, bs) do {                                                  \
        float* ws_ = (float*)(sm + ((bs) ? WS1_OFF : WS0_OFF));                \
        float* hs_ = (float*)(sm + ((bs) ? HS1_OFF : HS0_OFF));                \
        float4 hv0 = hb4[(tt) * 1024 + t];                                     \
        float4 hv1 = hb4[(tt) * 1024 + t + 512];                               \
        const int sbase = (tt) * 64 + jh;                                      \
        float* wrow = ws_ + ir * 68 + jh;                                      \
        _Pragma("unroll")                                                      \
        for (int k = 0; k < 4; k++) {                                          \
            const float4 s2v = *(const float4*)(s2s + sbase + k * 4);          \
            const float4 p2v = *(const float4*)(p2s + sbase + k * 4);          \
            const float4 q2v = *(const float4*)(q2s + sbase + k * 4);          \
            const int4 a_ = av[k];                                             \
            float4 wq; float w;                                                \
            w = 0.f; if (a_.x > 0) w = (s1r + s2v.x > 0.f) ? p1r * p2v.x : q1r * q2v.x; \
            zacc += w; wq.x = to_tf32(w);                                      \
            w = 0.f; if (a_.y > 0) w = (s1r + s2v.y > 0.f) ? p1r * p2v.y : q1r * q2v.y; \
            zacc += w; wq.y = to_tf32(w);                                      \
            w = 0.f; if (a_.z > 0) w = (s1r + s2v.z > 0.f) ? p1r * p2v.z : q1r * q2v.z; \
            zacc += w; wq.z = to_tf32(w);                                      \
            w = 0.f; if (a_.w > 0) w = (s1r + s2v.w > 0.f) ? p1r * p2v.w : q1r * q2v.w; \
            zacc += w; wq.w = to_tf32(w);                                      \
            *(float4*)(wrow + k * 4) = wq;                                     \
        }                                                                      \
        hv0.x = to_tf32(hv0.x); hv0.y = to_tf32(hv0.y);                        \
        hv0.z = to_tf32(hv0.z); hv0.w = to_tf32(hv0.w);                        \
        ((float4*)hs_)[(t >> 4) * 18 + (t & 15)] = hv0;                        \
        hv1.x = to_tf32(hv1.x); hv1.y = to_tf32(hv1.y);                        \
        hv1.z = to_tf32(hv1.z); hv1.w = to_tf32(hv1.w);                        \
        ((float4*)hs_)[((t + 512) >> 4) * 18 + (t & 15)] = hv1;                \
    } while (0)

    // prologue: gen tile 0 into buf0; issue adj(1)
    GEN_TILE(0, 0);
#pragma unroll
    for (int k = 0; k < 4; k++) avn[k] = ((const int4*)(adjrow + 64))[k];

    for (int tile = 0; tile < 16; tile++) {
        __syncthreads();   // gen(tile) visible; MMA(tile-1) done with buf(tile+1)

        if (tile < 15) {
#pragma unroll
            for (int k = 0; k < 4; k++) av[k] = avn[k];
            if (tile < 14) {
                const int* nx = adjrow + (tile + 2) * 64;
#pragma unroll
                for (int k = 0; k < 4; k++) avn[k] = ((const int4*)nx)[k];
            }
            GEN_TILE(tile + 1, (tile + 1) & 1);
        }

        // ---- MMA(tile) from buf(tile&1), ks-pipelined ----
        {
            float* ws_ = (float*)(sm + ((tile & 1) ? WS1_OFF : WS0_OFF));
            float* hs_ = (float*)(sm + ((tile & 1) ? HS1_OFF : HS0_OFF));

            uint32_t Ac[2][4], Bc[2][2];
#pragma unroll
            for (int mt = 0; mt < 2; mt++) {
                const int r0 = m0 + mt * 16 + g;
                Ac[mt][0] = __float_as_uint(ws_[r0 * 68 + tid4]);
                Ac[mt][1] = __float_as_uint(ws_[(r0 + 8) * 68 + tid4]);
                Ac[mt][2] = __float_as_uint(ws_[r0 * 68 + tid4 + 4]);
                Ac[mt][3] = __float_as_uint(ws_[(r0 + 8) * 68 + tid4 + 4]);
            }
#pragma unroll
            for (int nf = 0; nf < 2; nf++) {
                const int c0 = n0 + nf * 8 + g;
                Bc[nf][0] = __float_as_uint(hs_[tid4 * 72 + c0]);
                Bc[nf][1] = __float_as_uint(hs_[(tid4 + 4) * 72 + c0]);
            }
#pragma unroll
            for (int ks = 0; ks < 8; ks++) {
                uint32_t An[2][4], Bn[2][2];
                if (ks < 7) {
                    const int k0 = (ks + 1) * 8;
#pragma unroll
                    for (int mt = 0; mt < 2; mt++) {
                        const int r0 = m0 + mt * 16 + g;
                        An[mt][0] = __float_as_uint(ws_[r0 * 68 + k0 + tid4]);
                        An[mt][1] = __float_as_uint(ws_[(r0 + 8) * 68 + k0 + tid4]);
                        An[mt][2] = __float_as_uint(ws_[r0 * 68 + k0 + tid4 + 4]);
                        An[mt][3] = __float_as_uint(ws_[(r0 + 8) * 68 + k0 + tid4 + 4]);
                    }
#pragma unroll
                    for (int nf = 0; nf < 2; nf++) {
                        const int c0 = n0 + nf * 8 + g;
                        Bn[nf][0] = __float_as_uint(hs_[(k0 + tid4) * 72 + c0]);
                        Bn[nf][1] = __float_as_uint(hs_[(k0 + tid4 + 4) * 72 + c0]);
                    }
                }
#pragma unroll
                for (int nf = 0; nf < 2; nf++) {
                    mma_tf32(acc[0][nf], Ac[0], Bc[nf][0], Bc[nf][1]);
                    mma_tf32(acc[1][nf], Ac[1], Bc[nf][0], Bc[nf][1]);
                }
                if (ks < 7) {
#pragma unroll
                    for (int mt = 0; mt < 2; mt++)
#pragma unroll
                        for (int c = 0; c < 4; c++) Ac[mt][c] = An[mt][c];
#pragma unroll
                    for (int nf = 0; nf < 2; nf++) {
                        Bc[nf][0] = Bn[nf][0];
                        Bc[nf][1] = Bn[nf][1];
                    }
                }
            }
        }
    }

    // ---- z: combine the four quarter-partials per row ----
    zp[t] = zacc;
    __syncthreads();
    if (t < 128) zs[t] = (zp[t] + zp[t + 128]) + (zp[t + 256] + zp[t + 384]);
    __syncthreads();

    // ---- epilogue: normalize + ELU + store ----
#pragma unroll
    for (int mt = 0; mt < 2; mt++) {
        const int rA = m0 + mt * 16 + g;
        const int rB = rA + 8;
        const float invA = 1.f / zs[rA];
        const float invB = 1.f / zs[rB];
        float* outA = out + ((size_t)(b * N_ + i0 + rA)) * FO;
        float* outB = out + ((size_t)(b * N_ + i0 + rB)) * FO;
#pragma unroll
        for (int nf = 0; nf < 2; nf++) {
            const int col = n0 + nf * 8 + 2 * tid4;
            float v;
            float2 r;
            v = acc[mt][nf][0] * invA; r.x = (v > 0.f) ? v : expm1f(v);
            v = acc[mt][nf][1] * invA; r.y = (v > 0.f) ? v : expm1f(v);
            *(float2*)(outA + col) = r;
            v = acc[mt][nf][2] * invB; r.x = (v > 0.f) ? v : expm1f(v);
            v = acc[mt][nf][3] * invB; r.y = (v > 0.f) ? v : expm1f(v);
            *(float2*)(outB + col) = r;
        }
    }
}

// ---------------------------------------------------------------------------
extern "C" void kernel_launch(void* const* d_in, const int* in_sizes, int n_in,
                              void* d_out, int out_size) {
    const float* inp = (const float*)d_in[0];   // (16,1024,128) f32
    const int*   adj = (const int*)d_in[1];     // (16,1024,1024) i32
    const float* W   = (const float*)d_in[2];   // (128,64) f32
    const float* a   = (const float*)d_in[3];   // (128,1) f32
    float* out = (float*)d_out;                 // (16,1024,64) f32

    static int init = 0;
    if (!init) {
        cudaFuncSetAttribute(k_h_gemm, cudaFuncAttributeMaxDynamicSharedMemorySize,
                             SMEM_HG);
        cudaFuncSetAttribute(k_attn, cudaFuncAttributeMaxDynamicSharedMemorySize,
                             SMEM_ATTN);
        init = 1;
    }

    k_h_gemm<<<dim3(N_ / 64, B_), 256, SMEM_HG>>>(inp, W, a);
    k_attn<<<dim3(N_ / 128, B_), 512, SMEM_ATTN>>>(adj, out);
}

// round 7
// speedup vs baseline: 2.4863x; 1.0925x over previous
#include <cuda_runtime.h>
#include <cuda_bf16.h>
#include <math.h>
#include <stdint.h>

#define B_  16
#define N_  1024
#define FIN 128
#define FO  64
#define ALPHA_ 0.2f

// Scratch (device globals: no allocation allowed)
__device__ float g_h[B_ * N_ * FO];           // 4 MB  [b][j][o]
__device__ float g_p1[B_ * N_], g_q1[B_ * N_];
__device__ float g_p2[B_ * N_], g_q2[B_ * N_];

__device__ __forceinline__ float to_tf32(float x) {
    float r;
    asm("cvt.rna.tf32.f32 %0, %1;" : "=f"(r) : "f"(x));
    return r;
}
__device__ __forceinline__ void mma_tf32(float* d, const uint32_t* a,
                                         uint32_t b0, uint32_t b1) {
    asm volatile(
        "mma.sync.aligned.m16n8k8.row.col.f32.tf32.tf32.f32 "
        "{%0,%1,%2,%3}, {%4,%5,%6,%7}, {%8,%9}, {%0,%1,%2,%3};"
        : "+f"(d[0]), "+f"(d[1]), "+f"(d[2]), "+f"(d[3])
        : "r"(a[0]), "r"(a[1]), "r"(a[2]), "r"(a[3]), "r"(b0), "r"(b1));
}

// k_attn smem layout (accbuf[64][72] reuses [0, 18432) after the main loop)
#define HS_OFF   17408      // float hs[64][72] = 18432
#define P2_OFF   35840      // float p2s[1024]
#define Q2_OFF   39936
#define ZP_OFF   44032      // float zp[512]
#define ZS_OFF   46080      // float zs[64]
#define SMEM_ATTN 46336

#define SMEM_HG  66048      // sI 32K + sW 32K + sA 512

// ---------------------------------------------------------------------------
// Kernel 1: h = inp @ W, fused with per-node exps (p1,q1,p2,q2).
// ---------------------------------------------------------------------------
__global__ __launch_bounds__(256) void k_h_gemm(const float* __restrict__ inp,
                                                const float* __restrict__ W,
                                                const float* __restrict__ a) {
    extern __shared__ char sm1[];
    float* sI = (float*)sm1;             // [64][128]
    float* sW = (float*)(sm1 + 32768);   // [128][64]
    float* sA = (float*)(sm1 + 65536);   // [128]

    const int b    = blockIdx.y;
    const int row0 = blockIdx.x * 64;
    const int t    = threadIdx.x;

#pragma unroll
    for (int k = 0; k < 8; k++)
        ((float4*)sW)[t + k * 256] = ((const float4*)W)[t + k * 256];
    const float4* ip = (const float4*)(inp + ((size_t)b * N_ + row0) * FIN);
#pragma unroll
    for (int k = 0; k < 8; k++)
        ((float4*)sI)[t + k * 256] = ip[t + k * 256];
    if (t < 128) sA[t] = a[t];
    __syncthreads();

    const int ot = t & 15;
    const int rt = t >> 4;
    const int lane = t & 31;

    float acc[4][4];
#pragma unroll
    for (int r = 0; r < 4; r++)
#pragma unroll
        for (int c = 0; c < 4; c++) acc[r][c] = 0.f;

#pragma unroll 4
    for (int k = 0; k < FIN; k++) {
        const float4 w4 = *(const float4*)(sW + k * FO + ot * 4);
#pragma unroll
        for (int r = 0; r < 4; r++) {
            const float iv = sI[(rt * 4 + r) * FIN + k];
            acc[r][0] += iv * w4.x;
            acc[r][1] += iv * w4.y;
            acc[r][2] += iv * w4.z;
            acc[r][3] += iv * w4.w;
        }
    }

#pragma unroll
    for (int r = 0; r < 4; r++) {
        float* op = g_h + ((size_t)b * N_ + row0 + rt * 4 + r) * FO + ot * 4;
        *(float4*)op = make_float4(acc[r][0], acc[r][1], acc[r][2], acc[r][3]);
    }

    float s1p[4], s2p[4];
#pragma unroll
    for (int r = 0; r < 4; r++) {
        float v1 = 0.f, v2 = 0.f;
#pragma unroll
        for (int c = 0; c < 4; c++) {
            v1 += acc[r][c] * sA[ot * 4 + c];
            v2 += acc[r][c] * sA[64 + ot * 4 + c];
        }
        s1p[r] = v1; s2p[r] = v2;
    }
#pragma unroll
    for (int off = 8; off > 0; off >>= 1) {
#pragma unroll
        for (int r = 0; r < 4; r++) {
            s1p[r] += __shfl_xor_sync(0xffffffffu, s1p[r], off);
            s2p[r] += __shfl_xor_sync(0xffffffffu, s2p[r], off);
        }
    }
    if ((lane & 15) == 0) {
#pragma unroll
        for (int r = 0; r < 4; r++) {
            const int gi = b * N_ + row0 + rt * 4 + r;
            g_p1[gi] = __expf(s1p[r]);
            g_q1[gi] = __expf(ALPHA_ * s1p[r]);
            g_p2[gi] = __expf(s2p[r]);
            g_q2[gi] = __expf(ALPHA_ * s2p[r]);
        }
    }
}

// ---------------------------------------------------------------------------
// Kernel 2: attention via mma.sync tf32, k-split warp specialization.
// CTA: 64 i x 64 o, 512 thr, 16 warps = 2m x 2n x 4k, warp tile 32x32x16.
// w_ij = adj ? max(p1*p2, q1*q2) : 0   (== exp(leaky_relu(s1+s2)) masked).
// z accumulated exactly in fp32 during generation.
// ---------------------------------------------------------------------------
__global__ __launch_bounds__(512, 2) void k_attn(const int* __restrict__ adj,
                                                 float* __restrict__ out) {
    extern __shared__ char sm[];
    float* ws  = (float*)sm;               // [64][68]
    float* hs  = (float*)(sm + HS_OFF);    // [64][72]
    float* p2s = (float*)(sm + P2_OFF);
    float* q2s = (float*)(sm + Q2_OFF);
    float* zp  = (float*)(sm + ZP_OFF);
    float* zs  = (float*)(sm + ZS_OFF);
    float* accbuf = (float*)sm;            // [64][72], reuses ws/hs after loop

    const int b  = blockIdx.y;
    const int i0 = blockIdx.x * 64;
    const int t  = threadIdx.x;

    for (int idx = t; idx < N_; idx += 512) {
        const int gj = b * N_ + idx;
        p2s[idx] = g_p2[gj]; q2s[idx] = g_q2[gj];
    }

    // gen mapping: row ir (0..63), j-block jh (0..56 step 8); warp-uniform jh
    const int ir = t & 63;
    const int jh = (t >> 6) * 8;
    const int gi = b * N_ + i0 + ir;
    const float p1r = g_p1[gi], q1r = g_q1[gi];
    const int* adjrow = adj + (size_t)b * N_ * N_ + (size_t)(i0 + ir) * N_ + jh;

    // mma mapping: wid = kq*4 + mq*2 + nq ; warp tile 32x32, k-slice 16
    const int wid   = t >> 5;
    const int lane  = t & 31;
    const int g     = lane >> 2;
    const int tid4  = lane & 3;
    const int kq    = wid >> 2;
    const int m0    = ((wid >> 1) & 1) * 32;
    const int n0    = (wid & 1) * 32;
    const int kbase = kq * 16;

    float acc[2][4][4];
#pragma unroll
    for (int mt = 0; mt < 2; mt++)
#pragma unroll
        for (int nf = 0; nf < 4; nf++)
#pragma unroll
            for (int c = 0; c < 4; c++) acc[mt][nf][c] = 0.f;

    const float4* hb4 = (const float4*)(g_h + (size_t)b * N_ * FO);
    float zacc = 0.f;

    for (int tile = 0; tile < 16; tile++) {
        __syncthreads();   // prev MMA done reading ws/hs (tile0: tables ready)

        // issue global loads first (adj + h tile)
        const int4* ap = (const int4*)(adjrow + tile * 64);
        const int4 av0 = ap[0];
        const int4 av1 = ap[1];
        float4 hv0 = hb4[tile * 1024 + t];
        float4 hv1 = hb4[tile * 1024 + t + 512];

        // ---- generate w: row ir, j's [tile*64+jh, +8)  (tables broadcast) ----
        {
            const int tb = tile * 64 + jh;
            const float4 p2a = *(const float4*)(p2s + tb);
            const float4 q2a = *(const float4*)(q2s + tb);
            const float4 p2b = *(const float4*)(p2s + tb + 4);
            const float4 q2b = *(const float4*)(q2s + tb + 4);
            float4 wq0, wq1;
            float w;
            w = fmaxf(p1r * p2a.x, q1r * q2a.x); if (av0.x <= 0) w = 0.f;
            zacc += w; wq0.x = to_tf32(w);
            w = fmaxf(p1r * p2a.y, q1r * q2a.y); if (av0.y <= 0) w = 0.f;
            zacc += w; wq0.y = to_tf32(w);
            w = fmaxf(p1r * p2a.z, q1r * q2a.z); if (av0.z <= 0) w = 0.f;
            zacc += w; wq0.z = to_tf32(w);
            w = fmaxf(p1r * p2a.w, q1r * q2a.w); if (av0.w <= 0) w = 0.f;
            zacc += w; wq0.w = to_tf32(w);
            w = fmaxf(p1r * p2b.x, q1r * q2b.x); if (av1.x <= 0) w = 0.f;
            zacc += w; wq1.x = to_tf32(w);
            w = fmaxf(p1r * p2b.y, q1r * q2b.y); if (av1.y <= 0) w = 0.f;
            zacc += w; wq1.y = to_tf32(w);
            w = fmaxf(p1r * p2b.z, q1r * q2b.z); if (av1.z <= 0) w = 0.f;
            zacc += w; wq1.z = to_tf32(w);
            w = fmaxf(p1r * p2b.w, q1r * q2b.w); if (av1.w <= 0) w = 0.f;
            zacc += w; wq1.w = to_tf32(w);
            float* wrow = ws + ir * 68 + jh;
            *(float4*)wrow       = wq0;
            *(float4*)(wrow + 4) = wq1;
        }

        // ---- stage h tile [64 j][64 o] (tf32), stride 72 ----
        hv0.x = to_tf32(hv0.x); hv0.y = to_tf32(hv0.y);
        hv0.z = to_tf32(hv0.z); hv0.w = to_tf32(hv0.w);
        ((float4*)hs)[(t >> 4) * 18 + (t & 15)] = hv0;
        hv1.x = to_tf32(hv1.x); hv1.y = to_tf32(hv1.y);
        hv1.z = to_tf32(hv1.z); hv1.w = to_tf32(hv1.w);
        ((float4*)hs)[((t + 512) >> 4) * 18 + (t & 15)] = hv1;

        __syncthreads();

        // ---- MMA: this warp's 2 k-steps (k-slice kq) ----
#pragma unroll
        for (int s = 0; s < 2; s++) {
            const int k0 = kbase + s * 8;
            uint32_t A[2][4];
#pragma unroll
            for (int mt = 0; mt < 2; mt++) {
                const int r0 = m0 + mt * 16 + g;
                A[mt][0] = __float_as_uint(ws[r0 * 68 + k0 + tid4]);
                A[mt][1] = __float_as_uint(ws[(r0 + 8) * 68 + k0 + tid4]);
                A[mt][2] = __float_as_uint(ws[r0 * 68 + k0 + tid4 + 4]);
                A[mt][3] = __float_as_uint(ws[(r0 + 8) * 68 + k0 + tid4 + 4]);
            }
#pragma unroll
            for (int nf = 0; nf < 4; nf++) {
                const int c0 = n0 + nf * 8 + g;
                const uint32_t b0 = __float_as_uint(hs[(k0 + tid4) * 72 + c0]);
                const uint32_t b1 = __float_as_uint(hs[(k0 + tid4 + 4) * 72 + c0]);
                mma_tf32(acc[0][nf], A[0], b0, b1);
                mma_tf32(acc[1][nf], A[1], b0, b1);
            }
        }
    }

    // ---- z partials ----
    zp[t] = zacc;
    __syncthreads();    // also: all MMA done -> safe to overwrite ws/hs (accbuf)
    if (t < 64) {
        float v = 0.f;
#pragma unroll
        for (int q = 0; q < 8; q++) v += zp[t + 64 * q];
        zs[t] = v;
    }

    // ---- k-reduction across the 4 k-slice warp groups into accbuf ----
#pragma unroll
    for (int ph = 0; ph < 4; ph++) {
        if (ph > 0) __syncthreads();
        if (kq == ph) {
#pragma unroll
            for (int mt = 0; mt < 2; mt++) {
#pragma unroll
                for (int nf = 0; nf < 4; nf++) {
                    const int rA = m0 + mt * 16 + g;
                    const int cc = n0 + nf * 8 + 2 * tid4;
                    float2* pA = (float2*)(accbuf + rA * 72 + cc);
                    float2* pB = (float2*)(accbuf + (rA + 8) * 72 + cc);
                    if (ph == 0) {
                        *pA = make_float2(acc[mt][nf][0], acc[mt][nf][1]);
                        *pB = make_float2(acc[mt][nf][2], acc[mt][nf][3]);
                    } else {
                        float2 vA = *pA, vB = *pB;
                        vA.x += acc[mt][nf][0]; vA.y += acc[mt][nf][1];
                        vB.x += acc[mt][nf][2]; vB.y += acc[mt][nf][3];
                        *pA = vA; *pB = vB;
                    }
                }
            }
        }
    }
    __syncthreads();

    // ---- final: normalize + ELU + store (8 elems/thread) ----
    {
        const int row = t >> 3;
        const int c0  = (t & 7) * 8;
        const float inv = 1.f / zs[row];
        const float* src = accbuf + row * 72 + c0;
        float4 r;
        float v;
        float4 x = *(const float4*)src;
        v = x.x * inv; r.x = (v > 0.f) ? v : expm1f(v);
        v = x.y * inv; r.y = (v > 0.f) ? v : expm1f(v);
        v = x.z * inv; r.z = (v > 0.f) ? v : expm1f(v);
        v = x.w * inv; r.w = (v > 0.f) ? v : expm1f(v);
        float4* op = (float4*)(out + ((size_t)(b * N_ + i0 + row)) * FO + c0);
        op[0] = r;
        x = *(const float4*)(src + 4);
        v = x.x * inv; r.x = (v > 0.f) ? v : expm1f(v);
        v = x.y * inv; r.y = (v > 0.f) ? v : expm1f(v);
        v = x.z * inv; r.z = (v > 0.f) ? v : expm1f(v);
        v = x.w * inv; r.w = (v > 0.f) ? v : expm1f(v);
        op[1] = r;
    }
}

// ---------------------------------------------------------------------------
extern "C" void kernel_launch(void* const* d_in, const int* in_sizes, int n_in,
                              void* d_out, int out_size) {
    const float* inp = (const float*)d_in[0];   // (16,1024,128) f32
    const int*   adj = (const int*)d_in[1];     // (16,1024,1024) i32
    const float* W   = (const float*)d_in[2];   // (128,64) f32
    const float* a   = (const float*)d_in[3];   // (128,1) f32
    float* out = (float*)d_out;                 // (16,1024,64) f32

    static int init = 0;
    if (!init) {
        cudaFuncSetAttribute(k_h_gemm, cudaFuncAttributeMaxDynamicSharedMemorySize,
                             SMEM_HG);
        cudaFuncSetAttribute(k_attn, cudaFuncAttributeMaxDynamicSharedMemorySize,
                             SMEM_ATTN);
        init = 1;
    }

    k_h_gemm<<<dim3(N_ / 64, B_), 256, SMEM_HG>>>(inp, W, a);
    k_attn<<<dim3(N_ / 64, B_), 512, SMEM_ATTN>>>(adj, out);
}